// round 2
// baseline (speedup 1.0000x reference)
#include <cuda_runtime.h>

#define V      10
#define L      45          // V*(V-1)/2
#define NCOEF  14
#define RPB    64          // rows per block
#define TPB    256

// col index of the l-th strict-lower-triangle pair (np.tril_indices order: by row i, then col j)
__constant__ unsigned char c_col[L] = {
    0,
    0,1,
    0,1,2,
    0,1,2,3,
    0,1,2,3,4,
    0,1,2,3,4,5,
    0,1,2,3,4,5,6,
    0,1,2,3,4,5,6,7,
    0,1,2,3,4,5,6,7,8
};

__device__ __forceinline__ float warp_sum(float v) {
#pragma unroll
    for (int o = 16; o > 0; o >>= 1) v += __shfl_down_sync(0xffffffffu, v, o);
    return v;
}

__global__ __launch_bounds__(TPB)
void decor_kernel(const float* __restrict__ x,
                  const float* __restrict__ log_d,
                  const float* __restrict__ params,
                  float* __restrict__ out_all,
                  int n_rows)
{
    const int t = threadIdx.x;
    const int nblocks_main = (int)gridDim.x - 1;

    // ---------------- penalty block (last block): params-only ridge scalars ----------------
    if ((int)blockIdx.x == nblocks_main) {
        __shared__ float sp[NCOEF * L];
        __shared__ float red[3][TPB / 32];
        for (int i = t; i < NCOEF * L; i += TPB) sp[i] = params[i];
        __syncthreads();
        float par = 0.f, fir = 0.f, sec = 0.f;
        for (int i = t; i < NCOEF * L; i += TPB) { float v = sp[i]; par += v * v; }
        for (int i = t; i < (NCOEF - 1) * L; i += TPB) { float d = sp[i + L] - sp[i]; fir += d * d; }
        for (int i = t; i < (NCOEF - 2) * L; i += TPB) {
            float d = sp[i + 2 * L] - 2.f * sp[i + L] + sp[i];
            sec += d * d;
        }
        par = warp_sum(par); fir = warp_sum(fir); sec = warp_sum(sec);
        int lane = t & 31, w = t >> 5;
        if (lane == 0) { red[0][w] = sec; red[1][w] = fir; red[2][w] = par; }
        __syncthreads();
        if (w == 0) {
            float s = (lane < TPB / 32) ? red[0][lane] : 0.f;
            float f = (lane < TPB / 32) ? red[1][lane] : 0.f;
            float p = (lane < TPB / 32) ? red[2][lane] : 0.f;
            s = warp_sum(s); f = warp_sum(f); p = warp_sum(p);
            if (lane == 0) {
                float* tail = out_all + (size_t)n_rows * (V + V * V + V);
                tail[0] = s; tail[1] = f; tail[2] = p;
            }
        }
        return;
    }

    // ---------------- main blocks: 64 rows each ----------------
    __shared__ float s_params[NCOEF * L];   // [14][45]
    __shared__ float s_x[RPB * V];
    __shared__ float s_lam[RPB * L];

    const int base = (int)blockIdx.x * RPB;
    const int nr = min(RPB, n_rows - base);

    for (int i = t; i < NCOEF * L; i += TPB) s_params[i] = params[i];
    for (int i = t; i < nr * V; i += TPB)    s_x[i] = x[(size_t)base * V + i];
    __syncthreads();

    // lambda for each (row, pair): uniform cubic B-spline, closed form.
    // knots: spacing d = 10/11, x range [-5,5] -> interval index jj = floor((x+5)*11/10) in [0,10]
    const float INV_D = 11.0f / 10.0f;
    const float k6 = 1.0f / 6.0f;
    for (int idx = t; idx < nr * L; idx += TPB) {
        int r = idx / L, l = idx - r * L;
        float xv = s_x[r * V + c_col[l]];
        float xc = fminf(fmaxf(xv, -5.0f), 5.0f);
        float tt = (xc + 5.0f) * INV_D;
        float fj = fminf(floorf(tt), 10.0f);
        float u  = tt - fj;
        int   jj = (int)fj;
        float um = 1.0f - u;
        float u2 = u * u, u3 = u2 * u;
        float w0 = um * um * um * k6;
        float w1 = (3.0f * u3 - 6.0f * u2 + 4.0f) * k6;
        float w2 = (-3.0f * u3 + 3.0f * u2 + 3.0f * u + 1.0f) * k6;
        float w3 = u3 * k6;
        const float* p = s_params + l + jj * L;
        s_lam[idx] = w0 * p[0] + w1 * p[L] + w2 * p[2 * L] + w3 * p[3 * L];
    }
    __syncthreads();

    // M: identity + lambda in strict lower triangle. Coalesced float4 stores.
    float* Mbase = out_all + (size_t)n_rows * V + (size_t)base * (V * V);
    if (nr == RPB) {
        float4* M4 = (float4*)Mbase;
        for (int q = t; q < RPB * 25; q += TPB) {
            int r = q / 25, e = (q - r * 25) * 4;
            float4 v;
            float* vv = (float*)&v;
#pragma unroll
            for (int s = 0; s < 4; s++) {
                int ij = e + s, i = ij / 10, j = ij - i * 10;
                float val;
                if (i == j)      val = 1.0f;
                else if (i > j)  val = s_lam[r * L + (i * (i - 1)) / 2 + j];
                else             val = 0.0f;
                vv[s] = val;
            }
            M4[q] = v;
        }
    } else {
        for (int q = t; q < nr * (V * V); q += TPB) {
            int r = q / (V * V), ij = q - r * (V * V);
            int i = ij / 10, j = ij - i * 10;
            float val;
            if (i == j)      val = 1.0f;
            else if (i > j)  val = s_lam[r * L + (i * (i - 1)) / 2 + j];
            else             val = 0.0f;
            Mbase[q] = val;
        }
    }

    // out[n,i] = x[n,i] + sum_{j<i} lam * x[n,j]
    for (int idx = t; idx < nr * V; idx += TPB) {
        int r = idx / V, i = idx - r * V;
        float acc = s_x[idx];
        const float* lr = s_lam + r * L + (i * (i - 1)) / 2;
        for (int j = 0; j < i; j++) acc += lr[j] * s_x[r * V + j];
        out_all[(size_t)base * V + idx] = acc;
    }

    // log_d passthrough copy
    float* ldo = out_all + (size_t)n_rows * (V + V * V) + (size_t)base * V;
    const float* ldi = log_d + (size_t)base * V;
    if (nr == RPB) {
        const float4* s4 = (const float4*)ldi;
        float4* d4 = (float4*)ldo;
        for (int q = t; q < RPB * V / 4; q += TPB) d4[q] = s4[q];
    } else {
        for (int q = t; q < nr * V; q += TPB) ldo[q] = ldi[q];
    }
}

extern "C" void kernel_launch(void* const* d_in, const int* in_sizes, int n_in,
                              void* d_out, int out_size)
{
    const float* x      = (const float*)d_in[0];
    const float* log_d  = (const float*)d_in[1];
    const float* params = (const float*)d_in[2];
    float* out_all = (float*)d_out;

    int n_rows = in_sizes[0] / V;
    int main_blocks = (n_rows + RPB - 1) / RPB;
    decor_kernel<<<main_blocks + 1, TPB>>>(x, log_d, params, out_all, n_rows);
}

// round 3
// speedup vs baseline: 2.1092x; 2.1092x over previous
#include <cuda_runtime.h>

#define V      10
#define L      45          // V*(V-1)/2
#define NCOEF  14
#define RPB    256         // rows per block == threads per block
#define TPB    256
#define XPAD   11          // padded row stride for s_x (odd -> conflict-free)
#define PSTR   16          // padded coeff stride for transposed params

__device__ __forceinline__ float warp_sum(float v) {
#pragma unroll
    for (int o = 16; o > 0; o >>= 1) v += __shfl_down_sync(0xffffffffu, v, o);
    return v;
}

__global__ __launch_bounds__(TPB)
void decor_kernel(const float* __restrict__ x,
                  const float* __restrict__ log_d,
                  const float* __restrict__ params,
                  float* __restrict__ out_all,
                  int n_rows)
{
    const int t = threadIdx.x;
    const int nblocks_main = (int)gridDim.x - 1;

    // ---------------- penalty block (last block): params-only ridge scalars ----------------
    if ((int)blockIdx.x == nblocks_main) {
        __shared__ float sp[NCOEF * L];
        __shared__ float red[3][TPB / 32];
        for (int i = t; i < NCOEF * L; i += TPB) sp[i] = params[i];
        __syncthreads();
        float par = 0.f, fir = 0.f, sec = 0.f;
        for (int i = t; i < NCOEF * L; i += TPB) { float v = sp[i]; par += v * v; }
        for (int i = t; i < (NCOEF - 1) * L; i += TPB) { float d = sp[i + L] - sp[i]; fir += d * d; }
        for (int i = t; i < (NCOEF - 2) * L; i += TPB) {
            float d = sp[i + 2 * L] - 2.f * sp[i + L] + sp[i];
            sec += d * d;
        }
        par = warp_sum(par); fir = warp_sum(fir); sec = warp_sum(sec);
        int lane = t & 31, w = t >> 5;
        if (lane == 0) { red[0][w] = sec; red[1][w] = fir; red[2][w] = par; }
        __syncthreads();
        if (w == 0) {
            float s = (lane < TPB / 32) ? red[0][lane] : 0.f;
            float f = (lane < TPB / 32) ? red[1][lane] : 0.f;
            float p = (lane < TPB / 32) ? red[2][lane] : 0.f;
            s = warp_sum(s); f = warp_sum(f); p = warp_sum(p);
            if (lane == 0) {
                float* tail = out_all + (size_t)n_rows * (V + V * V + V);
                tail[0] = s; tail[1] = f; tail[2] = p;
            }
        }
        return;
    }

    // ---------------- main blocks: one thread per row ----------------
    __shared__ float s_p[L * PSTR];        // transposed params: s_p[l*16 + k] = params[k*L + l]
    __shared__ float s_x[RPB * XPAD];      // padded x tile

    const int base = (int)blockIdx.x * RPB;
    const int nr = min(RPB, n_rows - base);

    // transposed params load (630 elems, 3 iters/thread; conflict pattern irrelevant here)
    for (int i = t; i < NCOEF * L; i += TPB) {
        int k = i / L, l = i - k * L;
        s_p[l * PSTR + k] = params[i];
    }
    // coalesced x stage into padded layout
    for (int i = t; i < nr * V; i += TPB) {
        int r = i / V, c = i - r * V;
        s_x[r * XPAD + c] = x[(size_t)base * V + i];
    }
    __syncthreads();

    if (t < nr) {
        const int row = base + t;

        // registers: my x row
        float xr[V];
#pragma unroll
        for (int c = 0; c < V; c++) xr[c] = s_x[t * XPAD + c];

        // 9 basis evaluations (columns 0..8), then 45 lambdas via 4-term dots.
        // uniform cubic B-spline: d = 10/11, interval jj = clamp(floor((x+5)*11/10), 0, 10)
        const float INV_D = 11.0f / 10.0f;
        const float k6 = 1.0f / 6.0f;
        float lam[L];
#pragma unroll
        for (int j = 0; j < V - 1; j++) {
            float xc = fminf(fmaxf(xr[j], -5.0f), 5.0f);
            float tt = (xc + 5.0f) * INV_D;
            float fj = fminf(floorf(tt), 10.0f);
            float u  = tt - fj;
            int   jj = (int)fj;
            float um = 1.0f - u;
            float u2 = u * u, u3 = u2 * u;
            float w0 = um * um * um * k6;
            float w1 = (3.0f * u3 - 6.0f * u2 + 4.0f) * k6;
            float w2 = (-3.0f * u3 + 3.0f * u2 + 3.0f * u + 1.0f) * k6;
            float w3 = u3 * k6;
#pragma unroll
            for (int i = j + 1; i < V; i++) {
                const int l = (i * (i - 1)) / 2 + j;
                const float* p = s_p + l * PSTR + jj;   // conflict-free: jj in [0,10], PSTR=16
                lam[l] = w0 * p[0] + w1 * p[1] + w2 * p[2] + w3 * p[3];
            }
        }

        // out[n,i] = x_i + sum_{j<i} lam_{ij} x_j   (registers only)
        float o[V];
#pragma unroll
        for (int i = 0; i < V; i++) {
            float acc = xr[i];
#pragma unroll
            for (int j = 0; j < i; j++) acc += lam[(i * (i - 1)) / 2 + j] * xr[j];
            o[i] = acc;
        }
        // out row: 40B stride, 8B-aligned -> 5x float2
        float2* orow = (float2*)(out_all + (size_t)row * V);
#pragma unroll
        for (int q = 0; q < V / 2; q++) orow[q] = make_float2(o[2 * q], o[2 * q + 1]);

        // M row: identity + strict-lower lambdas; 400B/row, 16B-aligned -> 25x STG.128
        float4* Mrow = (float4*)(out_all + (size_t)n_rows * V + (size_t)row * (V * V));
#pragma unroll
        for (int q = 0; q < 25; q++) {
            float4 v;
            float* vv = (float*)&v;
#pragma unroll
            for (int s = 0; s < 4; s++) {
                const int ij = 4 * q + s;
                const int i = ij / V, j = ij - i * V;   // compile-time constants after unroll
                if (i == j)      vv[s] = 1.0f;
                else if (i > j)  vv[s] = lam[(i * (i - 1)) / 2 + j];
                else             vv[s] = 0.0f;
            }
            Mrow[q] = v;
        }
    }

    // log_d passthrough (coalesced float4 over this block's rows)
    {
        float* ldo = out_all + (size_t)n_rows * (V + V * V) + (size_t)base * V;
        const float* ldi = log_d + (size_t)base * V;
        int nfl = nr * V;
        if ((nfl & 3) == 0) {
            const float4* s4 = (const float4*)ldi;
            float4* d4 = (float4*)ldo;
            for (int q = t; q < nfl / 4; q += TPB) d4[q] = s4[q];
        } else {
            for (int q = t; q < nfl; q += TPB) ldo[q] = ldi[q];
        }
    }
}

extern "C" void kernel_launch(void* const* d_in, const int* in_sizes, int n_in,
                              void* d_out, int out_size)
{
    const float* x      = (const float*)d_in[0];
    const float* log_d  = (const float*)d_in[1];
    const float* params = (const float*)d_in[2];
    float* out_all = (float*)d_out;

    int n_rows = in_sizes[0] / V;
    int main_blocks = (n_rows + RPB - 1) / RPB;
    decor_kernel<<<main_blocks + 1, TPB>>>(x, log_d, params, out_all, n_rows);
}